// round 4
// baseline (speedup 1.0000x reference)
#include <cuda_runtime.h>

// GINNet on GB300: CSR-based aggregation + fp32x2 SIMT GEMM with fused BN-stat
// epilogues. BN+ReLU folded into per-column affine applied at next consumer.
// R3 change: monolithic 1-block scan (160us!) -> full-chip 3-phase scan (~15us).

#define NN 100000
#define NE 1600000
#define DD 128
#define NG 64
#define AS_STRIDE 132
#define GEMM_SMEM ((DD*DD + 64*AS_STRIDE + 2*DD) * 4)

#define SCAN_CHUNK 1024
#define SCAN_NB ((NN + SCAN_CHUNK - 1) / SCAN_CHUNK)   // 98

// ---------------- device scratch (allocation-free contract) ----------------
__device__ __align__(128) float g_z[NN * DD];   // aggregated features
__device__ __align__(128) float g_y[NN * DD];   // GEMM1 output (pre-BN1)
__device__ __align__(128) float g_h[NN * DD];   // GEMM2 output (pre-BN2)
__device__ int   g_cnt[NN];
__device__ int   g_ptr[NN + 1];
__device__ int   g_cur[NN];
__device__ int   g_srcs[NE];
__device__ int   g_bsum[SCAN_NB];
__device__ int   g_boff[SCAN_NB];
__device__ float g_ssum[6][DD];
__device__ float g_ssq[6][DD];
__device__ __align__(16) float g_cA[6][DD];     // BN+ReLU affine scale
__device__ __align__(16) float g_cC[6][DD];     // BN+ReLU affine shift
__device__ float g_gsum[NG * DD];
__device__ int   g_gcnt[NG];
__device__ int   g_flags[2];                    // [0]=edge idx is64, [1]=batch is64

// ---------------- helpers ----------------
__device__ __forceinline__ int get_idx(const void* p, long long i, int is64) {
    if (is64) return (int)((const long long*)p)[i];
    return ((const int*)p)[i];
}

__device__ __forceinline__ unsigned long long pk2(float v) {
    unsigned long long r;
    asm("mov.b64 %0, {%1, %1};" : "=l"(r) : "f"(v));
    return r;
}
__device__ __forceinline__ void upk2(unsigned long long p, float& lo, float& hi) {
    asm("mov.b64 {%0, %1}, %2;" : "=f"(lo), "=f"(hi) : "l"(p));
}
__device__ __forceinline__ void fma2(unsigned long long& d, unsigned long long a,
                                     unsigned long long b) {
    asm("fma.rn.f32x2 %0, %1, %2, %0;" : "+l"(d) : "l"(a), "l"(b));
}

// ---------------- setup kernels ----------------
__global__ void k_zero() {
    int i = blockIdx.x * blockDim.x + threadIdx.x;
    if (i < NN) g_cnt[i] = 0;
    if (i < 6 * DD) { ((float*)g_ssum)[i] = 0.f; ((float*)g_ssq)[i] = 0.f; }
    if (i < NG * DD) g_gsum[i] = 0.f;
    if (i < NG) g_gcnt[i] = 0;
}

// Detect whether index buffers are int64 or int32 (JAX x64 ambiguity).
// Sample only within the first half (safe for both widths).
__global__ void k_detect(const void* ei, const void* bt) {
    __shared__ int bad[2];
    if (threadIdx.x < 2) bad[threadIdx.x] = 0;
    __syncthreads();
    const long long* pe = (const long long*)ei;
    const long long* pb = (const long long*)bt;
    for (int i = threadIdx.x; i < 4096; i += blockDim.x) {
        long long v = pe[(long long)i * 390];      // within first NE int64 slots
        if (v < 0 || v >= NN) atomicOr(&bad[0], 1);
        long long w = pb[(long long)i * 12];       // within first NN/2 int64 slots
        if (w < 0 || w >= NG) atomicOr(&bad[1], 1);
    }
    __syncthreads();
    if (threadIdx.x == 0) { g_flags[0] = bad[0] ? 0 : 1; g_flags[1] = bad[1] ? 0 : 1; }
}

__global__ void k_count(const void* ei) {
    int e = blockIdx.x * blockDim.x + threadIdx.x;
    if (e >= NE) return;
    int is64 = g_flags[0];
    int t = get_idx(ei, (long long)NE + e, is64);
    atomicAdd(&g_cnt[t], 1);
}

// ---- 3-phase full-chip exclusive scan of g_cnt -> g_ptr/g_cur ----
// Phase A: per-block chunk reduction (coalesced).
__global__ void k_scanA() {
    __shared__ int wsum[8];
    int b = blockIdx.x, tid = threadIdx.x;
    int base = b * SCAN_CHUNK + tid * 4;
    int s = 0;
#pragma unroll
    for (int j = 0; j < 4; j++) {
        int i = base + j;
        if (i < NN) s += g_cnt[i];
    }
#pragma unroll
    for (int o = 16; o > 0; o >>= 1) s += __shfl_xor_sync(0xffffffffu, s, o);
    if ((tid & 31) == 0) wsum[tid >> 5] = s;
    __syncthreads();
    if (tid == 0) {
        int t = 0;
#pragma unroll
        for (int w = 0; w < 8; w++) t += wsum[w];
        g_bsum[b] = t;
    }
}

// Phase B: one small block scans the 98 block sums (exclusive).
__global__ void k_scanB() {
    __shared__ int sh[128];
    int t = threadIdx.x;
    sh[t] = (t < SCAN_NB) ? g_bsum[t] : 0;
    __syncthreads();
#pragma unroll
    for (int off = 1; off < 128; off <<= 1) {
        int v = (t >= off) ? sh[t - off] : 0;
        __syncthreads();
        sh[t] += v;
        __syncthreads();
    }
    if (t < SCAN_NB) g_boff[t] = (t == 0) ? 0 : sh[t - 1];
}

// Phase C: per-block hierarchical exclusive scan + offset, write g_ptr/g_cur.
__global__ void k_scanC() {
    __shared__ int wexc[8];
    int b = blockIdx.x, tid = threadIdx.x;
    int lane = tid & 31, wid = tid >> 5;
    int base = b * SCAN_CHUNK + tid * 4;
    int c[4];
    int tsum = 0;
#pragma unroll
    for (int j = 0; j < 4; j++) {
        int i = base + j;
        c[j] = (i < NN) ? g_cnt[i] : 0;
        tsum += c[j];
    }
    // inclusive warp scan of per-thread sums
    int incl = tsum;
#pragma unroll
    for (int o = 1; o < 32; o <<= 1) {
        int v = __shfl_up_sync(0xffffffffu, incl, o);
        if (lane >= o) incl += v;
    }
    if (lane == 31) wexc[wid] = incl;
    __syncthreads();
    if (tid == 0) {
        int run = 0;
#pragma unroll
        for (int w = 0; w < 8; w++) { int v = wexc[w]; wexc[w] = run; run += v; }
    }
    __syncthreads();
    int p = g_boff[b] + wexc[wid] + (incl - tsum);
#pragma unroll
    for (int j = 0; j < 4; j++) {
        int i = base + j;
        if (i < NN) {
            g_ptr[i] = p; g_cur[i] = p; p += c[j];
            if (i == NN - 1) g_ptr[NN] = p;
        }
    }
}

__global__ void k_fill(const void* ei) {
    int e = blockIdx.x * blockDim.x + threadIdx.x;
    if (e >= NE) return;
    int is64 = g_flags[0];
    int s = get_idx(ei, e, is64);
    int t = get_idx(ei, (long long)NE + e, is64);
    int pos = atomicAdd(&g_cur[t], 1);
    g_srcs[pos] = s;
}

// ---------------- aggregation: warp per node, no float atomics ----------------
// z[i] = (1+eps)*act(h[i]) + sum_{src in N(i)} act(h[src])
__global__ void k_agg(const float* __restrict__ x, int useX, int slot,
                      const float* __restrict__ epsArr, int layer) {
    int gt = blockIdx.x * blockDim.x + threadIdx.x;
    int node = gt >> 5;
    int lane = gt & 31;
    if (node >= NN) return;
    const float4* hin = useX ? (const float4*)x : (const float4*)g_h;
    float4 ca, cc;
    if (slot >= 0) {
        ca = ((const float4*)g_cA[slot])[lane];
        cc = ((const float4*)g_cC[slot])[lane];
    }
    float epsl = 1.f + epsArr[layer];
    int beg = g_ptr[node], end = g_ptr[node + 1];
    float4 v = hin[node * 32 + lane];
    if (slot >= 0) {
        v.x = fmaxf(fmaf(v.x, ca.x, cc.x), 0.f);
        v.y = fmaxf(fmaf(v.y, ca.y, cc.y), 0.f);
        v.z = fmaxf(fmaf(v.z, ca.z, cc.z), 0.f);
        v.w = fmaxf(fmaf(v.w, ca.w, cc.w), 0.f);
    }
    float4 acc = make_float4(v.x * epsl, v.y * epsl, v.z * epsl, v.w * epsl);
    for (int e = beg; e < end; e++) {
        int s = __ldg(&g_srcs[e]);
        float4 u = hin[s * 32 + lane];
        if (slot >= 0) {
            u.x = fmaxf(fmaf(u.x, ca.x, cc.x), 0.f);
            u.y = fmaxf(fmaf(u.y, ca.y, cc.y), 0.f);
            u.z = fmaxf(fmaf(u.z, ca.z, cc.z), 0.f);
            u.w = fmaxf(fmaf(u.w, ca.w, cc.w), 0.f);
        }
        acc.x += u.x; acc.y += u.y; acc.z += u.z; acc.w += u.w;
    }
    ((float4*)g_z)[node * 32 + lane] = acc;
}

// ---------------- GEMM: Y[64-row tile] = act(A) @ W, fused BN-stat epilogue ----
// 256 threads, each computes 4 rows x 8 cols via packed fma.rn.f32x2.
__global__ __launch_bounds__(256, 2)
void k_gemm(const float* __restrict__ W, int srcSel, int dstSel,
            int actSlot, int statSlot) {
    extern __shared__ float sm[];
    float* Bs = sm;                       // [128][128]
    float* As = sm + DD * DD;             // [64][AS_STRIDE]
    float* cs = As + 64 * AS_STRIDE;      // [128] col sums
    float* cq = cs + DD;                  // [128] col sumsq
    const float* A = srcSel ? g_y : g_z;
    float* Y = dstSel ? g_h : g_y;
    int tid = threadIdx.x;
    int tx = tid & 15, ty = tid >> 4;
    int mBase = blockIdx.x * 64;

    const float4* W4 = (const float4*)W;
    float4* Bs4 = (float4*)Bs;
#pragma unroll
    for (int i = 0; i < 16; i++) Bs4[tid + i * 256] = W4[tid + i * 256];

#pragma unroll
    for (int i = 0; i < 8; i++) {
        int lin = tid + i * 256;   // float4 index within tile
        int row = lin >> 5;
        int c4 = lin & 31;
        int grow = mBase + row;
        float4 v = make_float4(0.f, 0.f, 0.f, 0.f);
        if (grow < NN) v = ((const float4*)A)[grow * 32 + c4];
        if (actSlot >= 0) {
            float4 a = ((const float4*)g_cA[actSlot])[c4];
            float4 c = ((const float4*)g_cC[actSlot])[c4];
            v.x = fmaxf(fmaf(v.x, a.x, c.x), 0.f);
            v.y = fmaxf(fmaf(v.y, a.y, c.y), 0.f);
            v.z = fmaxf(fmaf(v.z, a.z, c.z), 0.f);
            v.w = fmaxf(fmaf(v.w, a.w, c.w), 0.f);
        }
        *(float4*)&As[row * AS_STRIDE + c4 * 4] = v;
    }
    if (tid < DD) { cs[tid] = 0.f; cq[tid] = 0.f; }
    __syncthreads();

    unsigned long long acc[4][4];
#pragma unroll
    for (int r = 0; r < 4; r++)
#pragma unroll
        for (int p = 0; p < 4; p++) acc[r][p] = 0ull;

    const float* Ar0 = &As[(ty * 4 + 0) * AS_STRIDE];
    const float* Ar1 = &As[(ty * 4 + 1) * AS_STRIDE];
    const float* Ar2 = &As[(ty * 4 + 2) * AS_STRIDE];
    const float* Ar3 = &As[(ty * 4 + 3) * AS_STRIDE];

#pragma unroll 8
    for (int k = 0; k < DD; k++) {
        unsigned long long a0 = pk2(Ar0[k]);
        unsigned long long a1 = pk2(Ar1[k]);
        unsigned long long a2 = pk2(Ar2[k]);
        unsigned long long a3 = pk2(Ar3[k]);
        const ulonglong2* brow = (const ulonglong2*)&Bs[k * DD];
        ulonglong2 b01 = brow[tx];        // cols 4tx..4tx+3
        ulonglong2 b23 = brow[16 + tx];   // cols 64+4tx..64+4tx+3
        fma2(acc[0][0], a0, b01.x); fma2(acc[0][1], a0, b01.y);
        fma2(acc[0][2], a0, b23.x); fma2(acc[0][3], a0, b23.y);
        fma2(acc[1][0], a1, b01.x); fma2(acc[1][1], a1, b01.y);
        fma2(acc[1][2], a1, b23.x); fma2(acc[1][3], a1, b23.y);
        fma2(acc[2][0], a2, b01.x); fma2(acc[2][1], a2, b01.y);
        fma2(acc[2][2], a2, b23.x); fma2(acc[2][3], a2, b23.y);
        fma2(acc[3][0], a3, b01.x); fma2(acc[3][1], a3, b01.y);
        fma2(acc[3][2], a3, b23.x); fma2(acc[3][3], a3, b23.y);
    }

    float ps[8], pq[8];
#pragma unroll
    for (int j = 0; j < 8; j++) { ps[j] = 0.f; pq[j] = 0.f; }

#pragma unroll
    for (int r = 0; r < 4; r++) {
        int grow = mBase + ty * 4 + r;
        if (grow < NN) {
            float f[8];
            upk2(acc[r][0], f[0], f[1]);
            upk2(acc[r][1], f[2], f[3]);
            upk2(acc[r][2], f[4], f[5]);
            upk2(acc[r][3], f[6], f[7]);
            ((float4*)Y)[grow * 32 + tx]      = make_float4(f[0], f[1], f[2], f[3]);
            ((float4*)Y)[grow * 32 + 16 + tx] = make_float4(f[4], f[5], f[6], f[7]);
#pragma unroll
            for (int j = 0; j < 8; j++) { ps[j] += f[j]; pq[j] += f[j] * f[j]; }
        }
    }
#pragma unroll
    for (int j = 0; j < 4; j++) {
        atomicAdd(&cs[tx * 4 + j], ps[j]);
        atomicAdd(&cq[tx * 4 + j], pq[j]);
        atomicAdd(&cs[64 + tx * 4 + j], ps[4 + j]);
        atomicAdd(&cq[64 + tx * 4 + j], pq[4 + j]);
    }
    __syncthreads();
    if (tid < DD) {
        atomicAdd(&g_ssum[statSlot][tid], cs[tid]);
        atomicAdd(&g_ssq[statSlot][tid], cq[tid]);
    }
}

// BN(train, biased var) folded into affine: y*a + c, ReLU applied by consumer.
__global__ void k_bnfin(const float* __restrict__ gamma,
                        const float* __restrict__ beta, int slot) {
    int d = threadIdx.x;
    float mean = g_ssum[slot][d] * (1.f / NN);
    float var = g_ssq[slot][d] * (1.f / NN) - mean * mean;
    float a = gamma[d] * rsqrtf(var + 1e-5f);
    g_cA[slot][d] = a;
    g_cC[slot][d] = beta[d] - mean * a;
}

// ---------------- readout ----------------
__global__ void k_nodeemb(float* __restrict__ out) {
    int i = blockIdx.x * blockDim.x + threadIdx.x;
    if (i >= NN * 32) return;
    int c4 = i & 31;
    float4 v = ((const float4*)g_h)[i];
    float4 a = ((const float4*)g_cA[5])[c4];
    float4 c = ((const float4*)g_cC[5])[c4];
    v.x = fmaxf(fmaf(v.x, a.x, c.x), 0.f);
    v.y = fmaxf(fmaf(v.y, a.y, c.y), 0.f);
    v.z = fmaxf(fmaf(v.z, a.z, c.z), 0.f);
    v.w = fmaxf(fmaf(v.w, a.w, c.w), 0.f);
    ((float4*)out)[i] = v;
}

__global__ void k_counts(const void* bt) {
    __shared__ int hist[NG];
    int tid = threadIdx.x;
    if (tid < NG) hist[tid] = 0;
    __syncthreads();
    int i = blockIdx.x * blockDim.x + tid;
    if (i < NN) {
        int b = get_idx(bt, i, g_flags[1]);
        atomicAdd(&hist[b], 1);
    }
    __syncthreads();
    if (tid < NG && hist[tid]) atomicAdd(&g_gcnt[tid], hist[tid]);
}

// Run-length accumulation over sorted batch -> few global atomics.
__global__ void k_gsum(const float* __restrict__ emb, const void* bt) {
    int d = threadIdx.x;            // 128 threads = columns
    int beg = blockIdx.x * 256;
    int end = min(beg + 256, NN);
    if (beg >= NN) return;
    int is64 = g_flags[1];
    int cur = get_idx(bt, beg, is64);
    float acc = 0.f;
    for (int i = beg; i < end; i++) {
        int b = get_idx(bt, i, is64);
        if (b != cur) { atomicAdd(&g_gsum[cur * DD + d], acc); acc = 0.f; cur = b; }
        acc += emb[i * DD + d];
    }
    atomicAdd(&g_gsum[cur * DD + d], acc);
}

__global__ void k_gemb(float* __restrict__ out) {
    int g = blockIdx.x, d = threadIdx.x;
    float cnt = (float)g_gcnt[g];
    float v = g_gsum[g * DD + d] / fmaxf(cnt, 1.f);
    float s = v * v;
#pragma unroll
    for (int o = 16; o > 0; o >>= 1) s += __shfl_xor_sync(0xffffffffu, s, o);
    __shared__ float red[4];
    if ((d & 31) == 0) red[d >> 5] = s;
    __syncthreads();
    float tot = red[0] + red[1] + red[2] + red[3];
    float nrm = fmaxf(sqrtf(tot), 1e-12f);
    out[NN * DD + g * DD + d] = v / nrm;
}

// ---------------- launch ----------------
extern "C" void kernel_launch(void* const* d_in, const int* in_sizes, int n_in,
                              void* d_out, int out_size) {
    const float* x  = (const float*)d_in[0];
    const void*  ei = d_in[1];
    const void*  bt = d_in[2];
    const float* W1 = (const float*)d_in[3];
    const float* g1 = (const float*)d_in[4];
    const float* b1 = (const float*)d_in[5];
    const float* W2 = (const float*)d_in[6];
    const float* g2 = (const float*)d_in[7];
    const float* b2 = (const float*)d_in[8];
    const float* eps = (const float*)d_in[9];
    float* out = (float*)d_out;
    (void)in_sizes; (void)n_in; (void)out_size;

    cudaFuncSetAttribute(k_gemm, cudaFuncAttributeMaxDynamicSharedMemorySize,
                         GEMM_SMEM);

    k_zero<<<(NN + 255) / 256, 256>>>();
    k_detect<<<1, 256>>>(ei, bt);
    k_count<<<(NE + 255) / 256, 256>>>(ei);
    k_scanA<<<SCAN_NB, 256>>>();
    k_scanB<<<1, 128>>>();
    k_scanC<<<SCAN_NB, 256>>>();
    k_fill<<<(NE + 255) / 256, 256>>>(ei);

    for (int l = 0; l < 3; l++) {
        k_agg<<<(NN * 32 + 255) / 256, 256>>>(x, l == 0 ? 1 : 0,
                                              l == 0 ? -1 : (2 * l - 1), eps, l);
        k_gemm<<<(NN + 63) / 64, 256, GEMM_SMEM>>>(W1 + l * DD * DD, 0, 0, -1, 2 * l);
        k_bnfin<<<1, DD>>>(g1 + l * DD, b1 + l * DD, 2 * l);
        k_gemm<<<(NN + 63) / 64, 256, GEMM_SMEM>>>(W2 + l * DD * DD, 1, 1, 2 * l,
                                                   2 * l + 1);
        k_bnfin<<<1, DD>>>(g2 + l * DD, b2 + l * DD, 2 * l + 1);
    }

    k_nodeemb<<<(NN * 32 + 255) / 256, 256>>>(out);
    k_counts<<<(NN + 255) / 256, 256>>>(bt);
    k_gsum<<<(NN + 255) / 256, 128>>>(out, bt);
    k_gemb<<<NG, DD>>>(out);
}

// round 7
// speedup vs baseline: 1.4314x; 1.4314x over previous
#include <cuda_runtime.h>
#include <cuda_bf16.h>
#include <cstdint>

// GINNet on GB300. R6: tcgen05 is unavailable (harness emits compute_103 PTX,
// arch-specific instructions rejected). GEMMs use arch-agnostic mma.sync
// (m16n8k16 bf16, 2-way split hi/lo, 3 accumulating passes) + ldmatrix.
// CSR aggregation + full-chip scan unchanged from the working R4 kernel.

#define NN 100000
#define NE 1600000
#define DD 128
#define NG 64

#define SCAN_CHUNK 1024
#define SCAN_NB ((NN + SCAN_CHUNK - 1) / SCAN_CHUNK)   // 98

#define GM_GRID ((NN + 127) / 128)                      // 782
// dyn smem: Ahi 32K | Alo 32K | Bhi 32K | Blo 32K
#define GM_SMEM 131072

// ---------------- device scratch (allocation-free contract) ----------------
__device__ __align__(128) float g_z[NN * DD];   // aggregated features
__device__ __align__(128) float g_y[NN * DD];   // GEMM1 output (pre-BN1)
__device__ __align__(128) float g_h[NN * DD];   // GEMM2 output (pre-BN2)
__device__ __align__(128) unsigned char g_wblk[6][65536]; // W^T bf16 hi|lo, swizzled [n][k]
__device__ int   g_cnt[NN];
__device__ int   g_ptr[NN + 1];
__device__ int   g_cur[NN];
__device__ int   g_srcs[NE];
__device__ int   g_bsum[SCAN_NB];
__device__ int   g_boff[SCAN_NB];
__device__ float g_ssum[6][DD];
__device__ float g_ssq[6][DD];
__device__ __align__(16) float g_cA[6][DD];     // BN+ReLU affine scale
__device__ __align__(16) float g_cC[6][DD];     // BN+ReLU affine shift
__device__ float g_gsum[NG * DD];
__device__ int   g_gcnt[NG];
__device__ int   g_flags[2];                    // [0]=edge idx is64, [1]=batch is64

// ---------------- PTX helpers (arch-agnostic, compile for compute_103) -----
__device__ __forceinline__ uint32_t smem_u32(const void* p) {
    uint32_t a;
    asm("{ .reg .u64 t; cvta.to.shared.u64 t, %1; cvt.u32.u64 %0, t; }"
        : "=r"(a) : "l"(p));
    return a;
}
__device__ __forceinline__ void ldsm4(uint32_t* r, uint32_t addr) {
    asm volatile("ldmatrix.sync.aligned.m8n8.x4.shared.b16 {%0,%1,%2,%3}, [%4];"
                 : "=r"(r[0]), "=r"(r[1]), "=r"(r[2]), "=r"(r[3]) : "r"(addr));
}
__device__ __forceinline__ void ldsm2(uint32_t* r, uint32_t addr) {
    asm volatile("ldmatrix.sync.aligned.m8n8.x2.shared.b16 {%0,%1}, [%2];"
                 : "=r"(r[0]), "=r"(r[1]) : "r"(addr));
}
__device__ __forceinline__ void mma16816(float* d, const uint32_t* a,
                                         const uint32_t* b) {
    asm volatile(
        "mma.sync.aligned.m16n8k16.row.col.f32.bf16.bf16.f32 "
        "{%0,%1,%2,%3}, {%4,%5,%6,%7}, {%8,%9}, {%0,%1,%2,%3};"
        : "+f"(d[0]), "+f"(d[1]), "+f"(d[2]), "+f"(d[3])
        : "r"(a[0]), "r"(a[1]), "r"(a[2]), "r"(a[3]), "r"(b[0]), "r"(b[1]));
}
__device__ __forceinline__ uint32_t pack_bf16x2(float lo, float hi) {
    __nv_bfloat16 l = __float2bfloat16(lo), h = __float2bfloat16(hi);
    return (uint32_t)__bfloat16_as_ushort(l) |
           ((uint32_t)__bfloat16_as_ushort(h) << 16);
}

// ---------------- misc helpers ----------------
__device__ __forceinline__ int get_idx(const void* p, long long i, int is64) {
    if (is64) return (int)((const long long*)p)[i];
    return ((const int*)p)[i];
}

// ---------------- setup kernels ----------------
__global__ void k_zero() {
    int i = blockIdx.x * blockDim.x + threadIdx.x;
    if (i < NN) g_cnt[i] = 0;
    if (i < 6 * DD) { ((float*)g_ssum)[i] = 0.f; ((float*)g_ssq)[i] = 0.f; }
    if (i < NG * DD) g_gsum[i] = 0.f;
    if (i < NG) g_gcnt[i] = 0;
}

__global__ void k_detect(const void* ei, const void* bt) {
    __shared__ int bad[2];
    if (threadIdx.x < 2) bad[threadIdx.x] = 0;
    __syncthreads();
    const long long* pe = (const long long*)ei;
    const long long* pb = (const long long*)bt;
    for (int i = threadIdx.x; i < 4096; i += blockDim.x) {
        long long v = pe[(long long)i * 390];
        if (v < 0 || v >= NN) atomicOr(&bad[0], 1);
        long long w = pb[(long long)i * 12];
        if (w < 0 || w >= NG) atomicOr(&bad[1], 1);
    }
    __syncthreads();
    if (threadIdx.x == 0) { g_flags[0] = bad[0] ? 0 : 1; g_flags[1] = bad[1] ? 0 : 1; }
}

// W^T split to bf16 hi/lo, [n][k] rows (256B) with xor-(n&7)<<4 swizzle.
__global__ void k_wprep(const float* __restrict__ W1, const float* __restrict__ W2) {
    int idx = blockIdx.x * blockDim.x + threadIdx.x;
    if (idx >= 6 * DD * DD) return;
    int m = idx >> 14;
    int r = idx & 16383;
    int n = r >> 7, k = r & 127;
    int l = m >> 1;
    const float* W = (m & 1) ? (W2 + l * DD * DD) : (W1 + l * DD * DD);
    float v = W[k * DD + n];                 // B[n][k] = W[k][n]
    __nv_bfloat16 h = __float2bfloat16(v);
    __nv_bfloat16 lo = __float2bfloat16(v - __bfloat162float(h));
    int off = n * 256 + k * 2;
    int sw = off ^ ((n & 7) << 4);
    *(__nv_bfloat16*)(g_wblk[m] + sw) = h;
    *(__nv_bfloat16*)(g_wblk[m] + 32768 + sw) = lo;
}

__global__ void k_count(const void* ei) {
    int e = blockIdx.x * blockDim.x + threadIdx.x;
    if (e >= NE) return;
    int t = get_idx(ei, (long long)NE + e, g_flags[0]);
    atomicAdd(&g_cnt[t], 1);
}

__global__ void k_scanA() {
    __shared__ int wsum[8];
    int b = blockIdx.x, tid = threadIdx.x;
    int base = b * SCAN_CHUNK + tid * 4;
    int s = 0;
#pragma unroll
    for (int j = 0; j < 4; j++) { int i = base + j; if (i < NN) s += g_cnt[i]; }
#pragma unroll
    for (int o = 16; o > 0; o >>= 1) s += __shfl_xor_sync(0xffffffffu, s, o);
    if ((tid & 31) == 0) wsum[tid >> 5] = s;
    __syncthreads();
    if (tid == 0) {
        int t = 0;
#pragma unroll
        for (int w = 0; w < 8; w++) t += wsum[w];
        g_bsum[b] = t;
    }
}

__global__ void k_scanB() {
    __shared__ int sh[128];
    int t = threadIdx.x;
    sh[t] = (t < SCAN_NB) ? g_bsum[t] : 0;
    __syncthreads();
#pragma unroll
    for (int off = 1; off < 128; off <<= 1) {
        int v = (t >= off) ? sh[t - off] : 0;
        __syncthreads();
        sh[t] += v;
        __syncthreads();
    }
    if (t < SCAN_NB) g_boff[t] = (t == 0) ? 0 : sh[t - 1];
}

__global__ void k_scanC() {
    __shared__ int wexc[8];
    int b = blockIdx.x, tid = threadIdx.x;
    int lane = tid & 31, wid = tid >> 5;
    int base = b * SCAN_CHUNK + tid * 4;
    int c[4];
    int tsum = 0;
#pragma unroll
    for (int j = 0; j < 4; j++) {
        int i = base + j;
        c[j] = (i < NN) ? g_cnt[i] : 0;
        tsum += c[j];
    }
    int incl = tsum;
#pragma unroll
    for (int o = 1; o < 32; o <<= 1) {
        int v = __shfl_up_sync(0xffffffffu, incl, o);
        if (lane >= o) incl += v;
    }
    if (lane == 31) wexc[wid] = incl;
    __syncthreads();
    if (tid == 0) {
        int run = 0;
#pragma unroll
        for (int w = 0; w < 8; w++) { int v = wexc[w]; wexc[w] = run; run += v; }
    }
    __syncthreads();
    int p = g_boff[b] + wexc[wid] + (incl - tsum);
#pragma unroll
    for (int j = 0; j < 4; j++) {
        int i = base + j;
        if (i < NN) {
            g_ptr[i] = p; g_cur[i] = p; p += c[j];
            if (i == NN - 1) g_ptr[NN] = p;
        }
    }
}

__global__ void k_fill(const void* ei) {
    int e = blockIdx.x * blockDim.x + threadIdx.x;
    if (e >= NE) return;
    int is64 = g_flags[0];
    int s = get_idx(ei, e, is64);
    int t = get_idx(ei, (long long)NE + e, is64);
    int pos = atomicAdd(&g_cur[t], 1);
    g_srcs[pos] = s;
}

// ---------------- aggregation: warp per node ----------------
__global__ void k_agg(const float* __restrict__ x, int useX, int slot,
                      const float* __restrict__ epsArr, int layer) {
    int gt = blockIdx.x * blockDim.x + threadIdx.x;
    int node = gt >> 5;
    int lane = gt & 31;
    if (node >= NN) return;
    const float4* hin = useX ? (const float4*)x : (const float4*)g_h;
    float4 ca, cc;
    if (slot >= 0) {
        ca = ((const float4*)g_cA[slot])[lane];
        cc = ((const float4*)g_cC[slot])[lane];
    }
    float epsl = 1.f + epsArr[layer];
    int beg = g_ptr[node], end = g_ptr[node + 1];
    float4 v = hin[node * 32 + lane];
    if (slot >= 0) {
        v.x = fmaxf(fmaf(v.x, ca.x, cc.x), 0.f);
        v.y = fmaxf(fmaf(v.y, ca.y, cc.y), 0.f);
        v.z = fmaxf(fmaf(v.z, ca.z, cc.z), 0.f);
        v.w = fmaxf(fmaf(v.w, ca.w, cc.w), 0.f);
    }
    float4 acc = make_float4(v.x * epsl, v.y * epsl, v.z * epsl, v.w * epsl);
    for (int e = beg; e < end; e++) {
        int s = __ldg(&g_srcs[e]);
        float4 u = hin[s * 32 + lane];
        if (slot >= 0) {
            u.x = fmaxf(fmaf(u.x, ca.x, cc.x), 0.f);
            u.y = fmaxf(fmaf(u.y, ca.y, cc.y), 0.f);
            u.z = fmaxf(fmaf(u.z, ca.z, cc.z), 0.f);
            u.w = fmaxf(fmaf(u.w, ca.w, cc.w), 0.f);
        }
        acc.x += u.x; acc.y += u.y; acc.z += u.z; acc.w += u.w;
    }
    ((float4*)g_z)[node * 32 + lane] = acc;
}

// ---------------- mma.sync GEMM: Y[128x128 tile] = act(A) @ W ---------------
// 256 thr / 8 warps, warp owns 16 rows. 3 passes: Ahi*Bhi + Ahi*Blo + Alo*Bhi.
// A/B staged bf16 in smem [row][k] 256B rows, xor-(row&7)<<4 swizzle.
__global__ __launch_bounds__(256, 1)
void k_gemmM(int srcSel, int dstSel, int actSlot, int statSlot, int wsel) {
    extern __shared__ unsigned char dyn[];
    __shared__ float cs[DD], cq[DD];
    unsigned char* Ahi = dyn;
    unsigned char* Alo = dyn + 32768;
    unsigned char* Bhi = dyn + 65536;
    unsigned char* Blo = dyn + 98304;

    int tid = threadIdx.x;
    int wid = tid >> 5, lane = tid & 31;
    int mBase = blockIdx.x * 128;
    const float* A = srcSel ? g_y : g_z;
    float* Y = dstSel ? g_h : g_y;

    if (tid < DD) { cs[tid] = 0.f; cq[tid] = 0.f; }

    // stage B: 64KB coalesced copy (hi|lo pre-swizzled)
    {
        const float4* src = (const float4*)g_wblk[wsel];
        float4* dst = (float4*)Bhi;   // Bhi and Blo contiguous
#pragma unroll
        for (int i = 0; i < 16; i++) dst[tid + i * 256] = src[tid + i * 256];
    }

    // stage A: 2 threads per row, 64 cols each; act + split + swizzled store
    {
        int r = tid >> 1, ch = tid & 1;
        int grow = mBase + r;
        bool valid = grow < NN;
        const float4* A4 = (const float4*)A;
#pragma unroll
        for (int c = 0; c < 8; c++) {
            int f4i = ch * 16 + c * 2;       // float4 idx within row (0..31)
            float4 v0 = make_float4(0.f, 0.f, 0.f, 0.f);
            float4 v1 = v0;
            if (valid) {
                v0 = A4[grow * 32 + f4i];
                v1 = A4[grow * 32 + f4i + 1];
            }
            if (actSlot >= 0 && valid) {
                float4 a0 = ((const float4*)g_cA[actSlot])[f4i];
                float4 c0 = ((const float4*)g_cC[actSlot])[f4i];
                float4 a1 = ((const float4*)g_cA[actSlot])[f4i + 1];
                float4 c1 = ((const float4*)g_cC[actSlot])[f4i + 1];
                v0.x = fmaxf(fmaf(v0.x, a0.x, c0.x), 0.f);
                v0.y = fmaxf(fmaf(v0.y, a0.y, c0.y), 0.f);
                v0.z = fmaxf(fmaf(v0.z, a0.z, c0.z), 0.f);
                v0.w = fmaxf(fmaf(v0.w, a0.w, c0.w), 0.f);
                v1.x = fmaxf(fmaf(v1.x, a1.x, c1.x), 0.f);
                v1.y = fmaxf(fmaf(v1.y, a1.y, c1.y), 0.f);
                v1.z = fmaxf(fmaf(v1.z, a1.z, c1.z), 0.f);
                v1.w = fmaxf(fmaf(v1.w, a1.w, c1.w), 0.f);
            }
            float f[8] = {v0.x, v0.y, v0.z, v0.w, v1.x, v1.y, v1.z, v1.w};
            uint4 hi, lo;
            uint32_t* hp = (uint32_t*)&hi;
            uint32_t* lp = (uint32_t*)&lo;
#pragma unroll
            for (int j = 0; j < 4; j++) {
                float x0 = f[j * 2], x1 = f[j * 2 + 1];
                __nv_bfloat16 h0 = __float2bfloat16(x0);
                __nv_bfloat16 h1 = __float2bfloat16(x1);
                hp[j] = (uint32_t)__bfloat16_as_ushort(h0) |
                        ((uint32_t)__bfloat16_as_ushort(h1) << 16);
                lp[j] = pack_bf16x2(x0 - __bfloat162float(h0),
                                    x1 - __bfloat162float(h1));
            }
            int off = r * 256 + (ch * 8 + c) * 16;
            int sw = off ^ ((r & 7) << 4);
            *(uint4*)(Ahi + sw) = hi;
            *(uint4*)(Alo + sw) = lo;
        }
    }
    __syncthreads();

    // ---- mma mainloop ----
    float acc[16][4];
#pragma unroll
    for (int n = 0; n < 16; n++)
#pragma unroll
        for (int j = 0; j < 4; j++) acc[n][j] = 0.f;

    int wrow = wid * 16;
    uint32_t aU = smem_u32(Ahi), bU = smem_u32(Bhi);
    // ldmatrix lane addressing
    int arow = wrow + (lane & 15);
    int akh = (lane >> 4) & 1;
    int aswb = ((arow & 7) << 4);
    int brow = lane & 7;
    int bkh = (lane >> 3) & 1;
    int bswb = ((brow & 7) << 4);

#pragma unroll
    for (int pass = 0; pass < 3; pass++) {
        uint32_t Ab = aU + (pass == 2 ? 32768u : 0u);
        uint32_t Bb = bU + (pass == 1 ? 32768u : 0u);
#pragma unroll
        for (int k = 0; k < 8; k++) {
            uint32_t af[4];
            int aoff = arow * 256 + k * 32 + akh * 16;
            ldsm4(af, Ab + (uint32_t)(aoff ^ aswb));
#pragma unroll
            for (int n = 0; n < 16; n++) {
                uint32_t bf[2];
                int boff = (n * 8 + brow) * 256 + k * 32 + bkh * 16;
                ldsm2(bf, Bb + (uint32_t)(boff ^ bswb));
                mma16816(acc[n], af, bf);
            }
        }
    }

    // ---- epilogue: store Y + BN column stats ----
    int r0 = mBase + wrow + (lane >> 2);
    int r1 = r0 + 8;
#pragma unroll
    for (int n = 0; n < 16; n++) {
        int col = n * 8 + 2 * (lane & 3);
        if (r0 < NN)
            *(float2*)&Y[r0 * DD + col] = make_float2(acc[n][0], acc[n][1]);
        if (r1 < NN)
            *(float2*)&Y[r1 * DD + col] = make_float2(acc[n][2], acc[n][3]);
        float s0 = acc[n][0] + acc[n][2];
        float s1 = acc[n][1] + acc[n][3];
        float q0 = acc[n][0] * acc[n][0] + acc[n][2] * acc[n][2];
        float q1 = acc[n][1] * acc[n][1] + acc[n][3] * acc[n][3];
#pragma unroll
        for (int o = 4; o <= 16; o <<= 1) {
            s0 += __shfl_xor_sync(0xffffffffu, s0, o);
            s1 += __shfl_xor_sync(0xffffffffu, s1, o);
            q0 += __shfl_xor_sync(0xffffffffu, q0, o);
            q1 += __shfl_xor_sync(0xffffffffu, q1, o);
        }
        if (lane < 4) {
            int c2 = n * 8 + 2 * lane;
            atomicAdd(&cs[c2], s0);
            atomicAdd(&cs[c2 + 1], s1);
            atomicAdd(&cq[c2], q0);
            atomicAdd(&cq[c2 + 1], q1);
        }
    }
    __syncthreads();
    if (tid < DD) {
        atomicAdd(&g_ssum[statSlot][tid], cs[tid]);
        atomicAdd(&g_ssq[statSlot][tid], cq[tid]);
    }
}

// BN(train, biased var) folded into affine.
__global__ void k_bnfin(const float* __restrict__ gamma,
                        const float* __restrict__ beta, int slot) {
    int d = threadIdx.x;
    float mean = g_ssum[slot][d] * (1.f / NN);
    float var = g_ssq[slot][d] * (1.f / NN) - mean * mean;
    float a = gamma[d] * rsqrtf(var + 1e-5f);
    g_cA[slot][d] = a;
    g_cC[slot][d] = beta[d] - mean * a;
}

// ---------------- readout ----------------
__global__ void k_nodeemb(float* __restrict__ out) {
    int i = blockIdx.x * blockDim.x + threadIdx.x;
    if (i >= NN * 32) return;
    int c4 = i & 31;
    float4 v = ((const float4*)g_h)[i];
    float4 a = ((const float4*)g_cA[5])[c4];
    float4 c = ((const float4*)g_cC[5])[c4];
    v.x = fmaxf(fmaf(v.x, a.x, c.x), 0.f);
    v.y = fmaxf(fmaf(v.y, a.y, c.y), 0.f);
    v.z = fmaxf(fmaf(v.z, a.z, c.z), 0.f);
    v.w = fmaxf(fmaf(v.w, a.w, c.w), 0.f);
    ((float4*)out)[i] = v;
}

__global__ void k_counts(const void* bt) {
    __shared__ int hist[NG];
    int tid = threadIdx.x;
    if (tid < NG) hist[tid] = 0;
    __syncthreads();
    int i = blockIdx.x * blockDim.x + tid;
    if (i < NN) {
        int b = get_idx(bt, i, g_flags[1]);
        atomicAdd(&hist[b], 1);
    }
    __syncthreads();
    if (tid < NG && hist[tid]) atomicAdd(&g_gcnt[tid], hist[tid]);
}

__global__ void k_gsum(const float* __restrict__ emb, const void* bt) {
    int d = threadIdx.x;
    int beg = blockIdx.x * 256;
    int end = min(beg + 256, NN);
    if (beg >= NN) return;
    int is64 = g_flags[1];
    int cur = get_idx(bt, beg, is64);
    float acc = 0.f;
    for (int i = beg; i < end; i++) {
        int b = get_idx(bt, i, is64);
        if (b != cur) { atomicAdd(&g_gsum[cur * DD + d], acc); acc = 0.f; cur = b; }
        acc += emb[i * DD + d];
    }
    atomicAdd(&g_gsum[cur * DD + d], acc);
}

__global__ void k_gemb(float* __restrict__ out) {
    int g = blockIdx.x, d = threadIdx.x;
    float cnt = (float)g_gcnt[g];
    float v = g_gsum[g * DD + d] / fmaxf(cnt, 1.f);
    float s = v * v;
#pragma unroll
    for (int o = 16; o > 0; o >>= 1) s += __shfl_xor_sync(0xffffffffu, s, o);
    __shared__ float red[4];
    if ((d & 31) == 0) red[d >> 5] = s;
    __syncthreads();
    float tot = red[0] + red[1] + red[2] + red[3];
    float nrm = fmaxf(sqrtf(tot), 1e-12f);
    out[NN * DD + g * DD + d] = v / nrm;
}

// ---------------- launch ----------------
extern "C" void kernel_launch(void* const* d_in, const int* in_sizes, int n_in,
                              void* d_out, int out_size) {
    const float* x  = (const float*)d_in[0];
    const void*  ei = d_in[1];
    const void*  bt = d_in[2];
    const float* W1 = (const float*)d_in[3];
    const float* g1 = (const float*)d_in[4];
    const float* b1 = (const float*)d_in[5];
    const float* W2 = (const float*)d_in[6];
    const float* g2 = (const float*)d_in[7];
    const float* b2 = (const float*)d_in[8];
    const float* eps = (const float*)d_in[9];
    float* out = (float*)d_out;
    (void)in_sizes; (void)n_in; (void)out_size;

    cudaFuncSetAttribute(k_gemmM, cudaFuncAttributeMaxDynamicSharedMemorySize,
                         GM_SMEM);

    k_zero<<<(NN + 255) / 256, 256>>>();
    k_detect<<<1, 256>>>(ei, bt);
    k_wprep<<<(6 * DD * DD + 255) / 256, 256>>>(W1, W2);
    k_count<<<(NE + 255) / 256, 256>>>(ei);
    k_scanA<<<SCAN_NB, 256>>>();
    k_scanB<<<1, 128>>>();
    k_scanC<<<SCAN_NB, 256>>>();
    k_fill<<<(NE + 255) / 256, 256>>>(ei);

    for (int l = 0; l < 3; l++) {
        k_agg<<<(NN * 32 + 255) / 256, 256>>>(x, l == 0 ? 1 : 0,
                                              l == 0 ? -1 : (2 * l - 1), eps, l);
        k_gemmM<<<GM_GRID, 256, GM_SMEM>>>(0, 0, -1, 2 * l, 2 * l);
        k_bnfin<<<1, DD>>>(g1 + l * DD, b1 + l * DD, 2 * l);
        k_gemmM<<<GM_GRID, 256, GM_SMEM>>>(1, 1, 2 * l, 2 * l + 1, 2 * l + 1);
        k_bnfin<<<1, DD>>>(g2 + l * DD, b2 + l * DD, 2 * l + 1);
    }

    k_nodeemb<<<(NN * 32 + 255) / 256, 256>>>(out);
    k_counts<<<(NN + 255) / 256, 256>>>(bt);
    k_gsum<<<(NN + 255) / 256, 128>>>(out, bt);
    k_gemb<<<NG, DD>>>(out);
}

// round 9
// speedup vs baseline: 1.6273x; 1.1368x over previous
#include <cuda_runtime.h>
#include <cuda_bf16.h>
#include <cstdint>

// GINNet on GB300. R8: GEMM mainloop restructured (B-fragment reuse across
// hi/lo passes via x4 ldmatrix, 3x fewer LDSM ops); BN-affine computation
// folded into consumer prologues (k_bnfin launches removed); detect folded
// into k_zero. mma.sync bf16 2-way split path (R7, proven) otherwise intact.

#define NN 100000
#define NE 1600000
#define DD 128
#define NG 64

#define SCAN_CHUNK 1024
#define SCAN_NB ((NN + SCAN_CHUNK - 1) / SCAN_CHUNK)   // 98

#define GM_GRID ((NN + 127) / 128)                      // 782
// dyn smem: Ahi 32K | Alo 32K | Bhi 32K | Blo 32K
#define GM_SMEM 131072

// ---------------- device scratch (allocation-free contract) ----------------
__device__ __align__(128) float g_z[NN * DD];   // aggregated features
__device__ __align__(128) float g_y[NN * DD];   // GEMM1 output (pre-BN1)
__device__ __align__(128) float g_h[NN * DD];   // GEMM2 output (pre-BN2)
__device__ __align__(128) unsigned char g_wblk[6][65536]; // W^T bf16 hi|lo, swizzled [n][k]
__device__ int   g_cnt[NN];
__device__ int   g_ptr[NN + 1];
__device__ int   g_cur[NN];
__device__ int   g_srcs[NE];
__device__ int   g_bsum[SCAN_NB];
__device__ int   g_boff[SCAN_NB];
__device__ float g_ssum[6][DD];
__device__ float g_ssq[6][DD];
__device__ float g_gsum[NG * DD];
__device__ int   g_gcnt[NG];
__device__ int   g_flags[2];                    // [0]=edge idx is64, [1]=batch is64

// ---------------- PTX helpers (arch-agnostic, compile for compute_103) -----
__device__ __forceinline__ uint32_t smem_u32(const void* p) {
    uint32_t a;
    asm("{ .reg .u64 t; cvta.to.shared.u64 t, %1; cvt.u32.u64 %0, t; }"
        : "=r"(a) : "l"(p));
    return a;
}
__device__ __forceinline__ void ldsm4(uint32_t* r, uint32_t addr) {
    asm volatile("ldmatrix.sync.aligned.m8n8.x4.shared.b16 {%0,%1,%2,%3}, [%4];"
                 : "=r"(r[0]), "=r"(r[1]), "=r"(r[2]), "=r"(r[3]) : "r"(addr));
}
__device__ __forceinline__ void mma16816(float* d, const uint32_t* a,
                                         const uint32_t* b) {
    asm volatile(
        "mma.sync.aligned.m16n8k16.row.col.f32.bf16.bf16.f32 "
        "{%0,%1,%2,%3}, {%4,%5,%6,%7}, {%8,%9}, {%0,%1,%2,%3};"
        : "+f"(d[0]), "+f"(d[1]), "+f"(d[2]), "+f"(d[3])
        : "r"(a[0]), "r"(a[1]), "r"(a[2]), "r"(a[3]), "r"(b[0]), "r"(b[1]));
}
__device__ __forceinline__ uint32_t pack_bf16x2(float lo, float hi) {
    __nv_bfloat16 l = __float2bfloat16(lo), h = __float2bfloat16(hi);
    return (uint32_t)__bfloat16_as_ushort(l) |
           ((uint32_t)__bfloat16_as_ushort(h) << 16);
}

// ---------------- misc helpers ----------------
__device__ __forceinline__ int get_idx(const void* p, long long i, int is64) {
    if (is64) return (int)((const long long*)p)[i];
    return ((const int*)p)[i];
}

// Per-block BN affine recompute: slot stats -> sA (scale), sC (shift).
__device__ __forceinline__ void bn_affine_block(int slot, const float* gm,
                                                const float* bt, float* sA,
                                                float* sC, int tid) {
    if (slot >= 0 && tid < DD) {
        float mean = g_ssum[slot][tid] * (1.f / NN);
        float var = g_ssq[slot][tid] * (1.f / NN) - mean * mean;
        float a = gm[tid] * rsqrtf(var + 1e-5f);
        sA[tid] = a;
        sC[tid] = bt[tid] - mean * a;
    }
}

// ---------------- setup kernels ----------------
__global__ void k_zero(const void* ei, const void* bt) {
    int i = blockIdx.x * blockDim.x + threadIdx.x;
    if (i < NN) g_cnt[i] = 0;
    if (i < 6 * DD) { ((float*)g_ssum)[i] = 0.f; ((float*)g_ssq)[i] = 0.f; }
    if (i < NG * DD) g_gsum[i] = 0.f;
    if (i < NG) g_gcnt[i] = 0;
    // block 0 additionally detects int64-vs-int32 index width
    if (blockIdx.x == 0) {
        __shared__ int bad[2];
        if (threadIdx.x < 2) bad[threadIdx.x] = 0;
        __syncthreads();
        const long long* pe = (const long long*)ei;
        const long long* pb = (const long long*)bt;
        for (int j = threadIdx.x; j < 4096; j += blockDim.x) {
            long long v = pe[(long long)j * 390];
            if (v < 0 || v >= NN) atomicOr(&bad[0], 1);
            long long w = pb[(long long)j * 12];
            if (w < 0 || w >= NG) atomicOr(&bad[1], 1);
        }
        __syncthreads();
        if (threadIdx.x == 0) {
            g_flags[0] = bad[0] ? 0 : 1;
            g_flags[1] = bad[1] ? 0 : 1;
        }
    }
}

// W^T split to bf16 hi/lo, [n][k] rows (256B) with xor-(n&7)<<4 swizzle.
__global__ void k_wprep(const float* __restrict__ W1, const float* __restrict__ W2) {
    int idx = blockIdx.x * blockDim.x + threadIdx.x;
    if (idx >= 6 * DD * DD) return;
    int m = idx >> 14;
    int r = idx & 16383;
    int n = r >> 7, k = r & 127;
    int l = m >> 1;
    const float* W = (m & 1) ? (W2 + l * DD * DD) : (W1 + l * DD * DD);
    float v = W[k * DD + n];                 // B[n][k] = W[k][n]
    __nv_bfloat16 h = __float2bfloat16(v);
    __nv_bfloat16 lo = __float2bfloat16(v - __bfloat162float(h));
    int off = n * 256 + k * 2;
    int sw = off ^ ((n & 7) << 4);
    *(__nv_bfloat16*)(g_wblk[m] + sw) = h;
    *(__nv_bfloat16*)(g_wblk[m] + 32768 + sw) = lo;
}

__global__ void k_count(const void* ei) {
    int e = blockIdx.x * blockDim.x + threadIdx.x;
    if (e >= NE) return;
    int t = get_idx(ei, (long long)NE + e, g_flags[0]);
    atomicAdd(&g_cnt[t], 1);
}

__global__ void k_scanA() {
    __shared__ int wsum[8];
    int b = blockIdx.x, tid = threadIdx.x;
    int base = b * SCAN_CHUNK + tid * 4;
    int s = 0;
#pragma unroll
    for (int j = 0; j < 4; j++) { int i = base + j; if (i < NN) s += g_cnt[i]; }
#pragma unroll
    for (int o = 16; o > 0; o >>= 1) s += __shfl_xor_sync(0xffffffffu, s, o);
    if ((tid & 31) == 0) wsum[tid >> 5] = s;
    __syncthreads();
    if (tid == 0) {
        int t = 0;
#pragma unroll
        for (int w = 0; w < 8; w++) t += wsum[w];
        g_bsum[b] = t;
    }
}

__global__ void k_scanB() {
    __shared__ int sh[128];
    int t = threadIdx.x;
    sh[t] = (t < SCAN_NB) ? g_bsum[t] : 0;
    __syncthreads();
#pragma unroll
    for (int off = 1; off < 128; off <<= 1) {
        int v = (t >= off) ? sh[t - off] : 0;
        __syncthreads();
        sh[t] += v;
        __syncthreads();
    }
    if (t < SCAN_NB) g_boff[t] = (t == 0) ? 0 : sh[t - 1];
}

__global__ void k_scanC() {
    __shared__ int wexc[8];
    int b = blockIdx.x, tid = threadIdx.x;
    int lane = tid & 31, wid = tid >> 5;
    int base = b * SCAN_CHUNK + tid * 4;
    int c[4];
    int tsum = 0;
#pragma unroll
    for (int j = 0; j < 4; j++) {
        int i = base + j;
        c[j] = (i < NN) ? g_cnt[i] : 0;
        tsum += c[j];
    }
    int incl = tsum;
#pragma unroll
    for (int o = 1; o < 32; o <<= 1) {
        int v = __shfl_up_sync(0xffffffffu, incl, o);
        if (lane >= o) incl += v;
    }
    if (lane == 31) wexc[wid] = incl;
    __syncthreads();
    if (tid == 0) {
        int run = 0;
#pragma unroll
        for (int w = 0; w < 8; w++) { int v = wexc[w]; wexc[w] = run; run += v; }
    }
    __syncthreads();
    int p = g_boff[b] + wexc[wid] + (incl - tsum);
#pragma unroll
    for (int j = 0; j < 4; j++) {
        int i = base + j;
        if (i < NN) {
            g_ptr[i] = p; g_cur[i] = p; p += c[j];
            if (i == NN - 1) g_ptr[NN] = p;
        }
    }
}

__global__ void k_fill(const void* ei) {
    int e = blockIdx.x * blockDim.x + threadIdx.x;
    if (e >= NE) return;
    int is64 = g_flags[0];
    int s = get_idx(ei, e, is64);
    int t = get_idx(ei, (long long)NE + e, is64);
    int pos = atomicAdd(&g_cur[t], 1);
    g_srcs[pos] = s;
}

// ---------------- aggregation: warp per node ----------------
__global__ void k_agg(const float* __restrict__ x, int useX, int slot,
                      const float* __restrict__ gm, const float* __restrict__ bt,
                      const float* __restrict__ epsArr, int layer) {
    __shared__ __align__(16) float sAf[DD], sCf[DD];
    int tid = threadIdx.x;
    bn_affine_block(slot, gm, bt, sAf, sCf, tid);
    __syncthreads();

    int gt = blockIdx.x * blockDim.x + tid;
    int node = gt >> 5;
    int lane = gt & 31;
    if (node >= NN) return;
    const float4* hin = useX ? (const float4*)x : (const float4*)g_h;
    float4 ca, cc;
    if (slot >= 0) {
        ca = ((const float4*)sAf)[lane];
        cc = ((const float4*)sCf)[lane];
    }
    float epsl = 1.f + epsArr[layer];
    int beg = g_ptr[node], end = g_ptr[node + 1];
    float4 v = hin[node * 32 + lane];
    if (slot >= 0) {
        v.x = fmaxf(fmaf(v.x, ca.x, cc.x), 0.f);
        v.y = fmaxf(fmaf(v.y, ca.y, cc.y), 0.f);
        v.z = fmaxf(fmaf(v.z, ca.z, cc.z), 0.f);
        v.w = fmaxf(fmaf(v.w, ca.w, cc.w), 0.f);
    }
    float4 acc = make_float4(v.x * epsl, v.y * epsl, v.z * epsl, v.w * epsl);
    for (int e = beg; e < end; e++) {
        int s = __ldg(&g_srcs[e]);
        float4 u = hin[s * 32 + lane];
        if (slot >= 0) {
            u.x = fmaxf(fmaf(u.x, ca.x, cc.x), 0.f);
            u.y = fmaxf(fmaf(u.y, ca.y, cc.y), 0.f);
            u.z = fmaxf(fmaf(u.z, ca.z, cc.z), 0.f);
            u.w = fmaxf(fmaf(u.w, ca.w, cc.w), 0.f);
        }
        acc.x += u.x; acc.y += u.y; acc.z += u.z; acc.w += u.w;
    }
    ((float4*)g_z)[node * 32 + lane] = acc;
}

// ---------------- mma.sync GEMM: Y[128x128 tile] = act(A) @ W ---------------
// 256 thr / 8 warps, warp owns 16 rows. Per k-slice: load all Bhi frags (8x
// ldsm4 -> 32 regs), run hi*hi AND lo*hi passes, then overwrite with Blo for
// hi*lo. 144 ldsm4/warp total (was 456 LDSM ops in R7).
__global__ __launch_bounds__(256, 1)
void k_gemmM(int srcSel, int dstSel, const float* __restrict__ gm,
             const float* __restrict__ bt, int actSlot, int statSlot, int wsel) {
    extern __shared__ unsigned char dyn[];
    __shared__ float cs[DD], cq[DD];
    __shared__ __align__(16) float sAf[DD], sCf[DD];
    unsigned char* Ahi = dyn;
    unsigned char* Alo = dyn + 32768;
    unsigned char* Bhi = dyn + 65536;

    int tid = threadIdx.x;
    int wid = tid >> 5, lane = tid & 31;
    int mBase = blockIdx.x * 128;
    const float* A = srcSel ? g_y : g_z;
    float* Y = dstSel ? g_h : g_y;

    if (tid < DD) { cs[tid] = 0.f; cq[tid] = 0.f; }
    bn_affine_block(actSlot, gm, bt, sAf, sCf, tid);

    // stage B: 64KB coalesced copy (hi|lo pre-swizzled, contiguous)
    {
        const float4* src = (const float4*)g_wblk[wsel];
        float4* dst = (float4*)Bhi;
#pragma unroll
        for (int i = 0; i < 16; i++) dst[tid + i * 256] = src[tid + i * 256];
    }
    __syncthreads();

    // stage A: 2 threads per row, 64 cols each; act + split + swizzled store
    {
        int r = tid >> 1, ch = tid & 1;
        int grow = mBase + r;
        bool valid = grow < NN;
        const float4* A4 = (const float4*)A;
#pragma unroll
        for (int c = 0; c < 8; c++) {
            int f4i = ch * 16 + c * 2;       // float4 idx within row (0..31)
            float4 v0 = make_float4(0.f, 0.f, 0.f, 0.f);
            float4 v1 = v0;
            if (valid) {
                v0 = A4[grow * 32 + f4i];
                v1 = A4[grow * 32 + f4i + 1];
            }
            if (actSlot >= 0 && valid) {
                float4 a0 = ((const float4*)sAf)[f4i];
                float4 c0 = ((const float4*)sCf)[f4i];
                float4 a1 = ((const float4*)sAf)[f4i + 1];
                float4 c1 = ((const float4*)sCf)[f4i + 1];
                v0.x = fmaxf(fmaf(v0.x, a0.x, c0.x), 0.f);
                v0.y = fmaxf(fmaf(v0.y, a0.y, c0.y), 0.f);
                v0.z = fmaxf(fmaf(v0.z, a0.z, c0.z), 0.f);
                v0.w = fmaxf(fmaf(v0.w, a0.w, c0.w), 0.f);
                v1.x = fmaxf(fmaf(v1.x, a1.x, c1.x), 0.f);
                v1.y = fmaxf(fmaf(v1.y, a1.y, c1.y), 0.f);
                v1.z = fmaxf(fmaf(v1.z, a1.z, c1.z), 0.f);
                v1.w = fmaxf(fmaf(v1.w, a1.w, c1.w), 0.f);
            }
            float f[8] = {v0.x, v0.y, v0.z, v0.w, v1.x, v1.y, v1.z, v1.w};
            uint4 hi, lo;
            uint32_t* hp = (uint32_t*)&hi;
            uint32_t* lp = (uint32_t*)&lo;
#pragma unroll
            for (int j = 0; j < 4; j++) {
                float x0 = f[j * 2], x1 = f[j * 2 + 1];
                __nv_bfloat16 h0 = __float2bfloat16(x0);
                __nv_bfloat16 h1 = __float2bfloat16(x1);
                hp[j] = (uint32_t)__bfloat16_as_ushort(h0) |
                        ((uint32_t)__bfloat16_as_ushort(h1) << 16);
                lp[j] = pack_bf16x2(x0 - __bfloat162float(h0),
                                    x1 - __bfloat162float(h1));
            }
            int off = r * 256 + (ch * 8 + c) * 16;
            int sw = off ^ ((r & 7) << 4);
            *(uint4*)(Ahi + sw) = hi;
            *(uint4*)(Alo + sw) = lo;
        }
    }
    __syncthreads();

    // ---- mma mainloop ----
    float acc[16][4];
#pragma unroll
    for (int n = 0; n < 16; n++)
#pragma unroll
        for (int j = 0; j < 4; j++) acc[n][j] = 0.f;

    int wrow = wid * 16;
    uint32_t aU = smem_u32(Ahi), bU = smem_u32(Bhi);
    // A ldmatrix lane addressing (proven in R7)
    int arow = wrow + (lane & 15);
    int akh = (lane >> 4) & 1;
    int aswb = ((arow & 7) << 4);
    // B x4 lane addressing: matrices = (tile 2p+ntp, khalf bkh)
    int ntp = (lane >> 4) & 1;
    int bkh = (lane >> 3) & 1;
    int brow = lane & 7;
    int bswb = (brow << 4);

#pragma unroll
    for (int k = 0; k < 8; k++) {
        uint32_t afH[4], afL[4];
        {
            int aoff = arow * 256 + k * 32 + akh * 16;
            ldsm4(afH, aU + (uint32_t)(aoff ^ aswb));
            ldsm4(afL, aU + 32768u + (uint32_t)(aoff ^ aswb));
        }
        uint32_t bf[32];
#pragma unroll
        for (int p = 0; p < 8; p++) {
            int boff = ((2 * p + ntp) * 8 + brow) * 256 + k * 32 + bkh * 16;
            ldsm4(&bf[p * 4], bU + (uint32_t)(boff ^ bswb));
        }
#pragma unroll
        for (int p = 0; p < 8; p++) {           // hi * hi
            mma16816(acc[2 * p], afH, &bf[4 * p]);
            mma16816(acc[2 * p + 1], afH, &bf[4 * p + 2]);
        }
#pragma unroll
        for (int p = 0; p < 8; p++) {           // lo * hi
            mma16816(acc[2 * p], afL, &bf[4 * p]);
            mma16816(acc[2 * p + 1], afL, &bf[4 * p + 2]);
        }
#pragma unroll
        for (int p = 0; p < 8; p++) {
            int boff = ((2 * p + ntp) * 8 + brow) * 256 + k * 32 + bkh * 16;
            ldsm4(&bf[p * 4], bU + 32768u + (uint32_t)(boff ^ bswb));
        }
#pragma unroll
        for (int p = 0; p < 8; p++) {           // hi * lo
            mma16816(acc[2 * p], afH, &bf[4 * p]);
            mma16816(acc[2 * p + 1], afH, &bf[4 * p + 2]);
        }
    }

    // ---- epilogue: store Y + BN column stats ----
    int r0 = mBase + wrow + (lane >> 2);
    int r1 = r0 + 8;
#pragma unroll
    for (int n = 0; n < 16; n++) {
        int col = n * 8 + 2 * (lane & 3);
        if (r0 < NN)
            *(float2*)&Y[r0 * DD + col] = make_float2(acc[n][0], acc[n][1]);
        if (r1 < NN)
            *(float2*)&Y[r1 * DD + col] = make_float2(acc[n][2], acc[n][3]);
        float s0 = acc[n][0] + acc[n][2];
        float s1 = acc[n][1] + acc[n][3];
        float q0 = acc[n][0] * acc[n][0] + acc[n][2] * acc[n][2];
        float q1 = acc[n][1] * acc[n][1] + acc[n][3] * acc[n][3];
#pragma unroll
        for (int o = 4; o <= 16; o <<= 1) {
            s0 += __shfl_xor_sync(0xffffffffu, s0, o);
            s1 += __shfl_xor_sync(0xffffffffu, s1, o);
            q0 += __shfl_xor_sync(0xffffffffu, q0, o);
            q1 += __shfl_xor_sync(0xffffffffu, q1, o);
        }
        if (lane < 4) {
            int c2 = n * 8 + 2 * lane;
            atomicAdd(&cs[c2], s0);
            atomicAdd(&cs[c2 + 1], s1);
            atomicAdd(&cq[c2], q0);
            atomicAdd(&cq[c2 + 1], q1);
        }
    }
    __syncthreads();
    if (tid < DD) {
        atomicAdd(&g_ssum[statSlot][tid], cs[tid]);
        atomicAdd(&g_ssq[statSlot][tid], cq[tid]);
    }
}

// ---------------- readout ----------------
__global__ void k_nodeemb(float* __restrict__ out, const float* __restrict__ gm,
                          const float* __restrict__ bt) {
    __shared__ __align__(16) float sAf[DD], sCf[DD];
    int tid = threadIdx.x;
    bn_affine_block(5, gm, bt, sAf, sCf, tid);
    __syncthreads();
    int i = blockIdx.x * blockDim.x + tid;
    if (i >= NN * 32) return;
    int c4 = i & 31;
    float4 v = ((const float4*)g_h)[i];
    float4 a = ((const float4*)sAf)[c4];
    float4 c = ((const float4*)sCf)[c4];
    v.x = fmaxf(fmaf(v.x, a.x, c.x), 0.f);
    v.y = fmaxf(fmaf(v.y, a.y, c.y), 0.f);
    v.z = fmaxf(fmaf(v.z, a.z, c.z), 0.f);
    v.w = fmaxf(fmaf(v.w, a.w, c.w), 0.f);
    ((float4*)out)[i] = v;
}

__global__ void k_counts(const void* bt) {
    __shared__ int hist[NG];
    int tid = threadIdx.x;
    if (tid < NG) hist[tid] = 0;
    __syncthreads();
    int i = blockIdx.x * blockDim.x + tid;
    if (i < NN) {
        int b = get_idx(bt, i, g_flags[1]);
        atomicAdd(&hist[b], 1);
    }
    __syncthreads();
    if (tid < NG && hist[tid]) atomicAdd(&g_gcnt[tid], hist[tid]);
}

__global__ void k_gsum(const float* __restrict__ emb, const void* bt) {
    int d = threadIdx.x;
    int beg = blockIdx.x * 256;
    int end = min(beg + 256, NN);
    if (beg >= NN) return;
    int is64 = g_flags[1];
    int cur = get_idx(bt, beg, is64);
    float acc = 0.f;
    for (int i = beg; i < end; i++) {
        int b = get_idx(bt, i, is64);
        if (b != cur) { atomicAdd(&g_gsum[cur * DD + d], acc); acc = 0.f; cur = b; }
        acc += emb[i * DD + d];
    }
    atomicAdd(&g_gsum[cur * DD + d], acc);
}

__global__ void k_gemb(float* __restrict__ out) {
    int g = blockIdx.x, d = threadIdx.x;
    float cnt = (float)g_gcnt[g];
    float v = g_gsum[g * DD + d] / fmaxf(cnt, 1.f);
    float s = v * v;
#pragma unroll
    for (int o = 16; o > 0; o >>= 1) s += __shfl_xor_sync(0xffffffffu, s, o);
    __shared__ float red[4];
    if ((d & 31) == 0) red[d >> 5] = s;
    __syncthreads();
    float tot = red[0] + red[1] + red[2] + red[3];
    float nrm = fmaxf(sqrtf(tot), 1e-12f);
    out[NN * DD + g * DD + d] = v / nrm;
}

// ---------------- launch ----------------
extern "C" void kernel_launch(void* const* d_in, const int* in_sizes, int n_in,
                              void* d_out, int out_size) {
    const float* x  = (const float*)d_in[0];
    const void*  ei = d_in[1];
    const void*  bt = d_in[2];
    const float* W1 = (const float*)d_in[3];
    const float* g1 = (const float*)d_in[4];
    const float* b1 = (const float*)d_in[5];
    const float* W2 = (const float*)d_in[6];
    const float* g2 = (const float*)d_in[7];
    const float* b2 = (const float*)d_in[8];
    const float* eps = (const float*)d_in[9];
    float* out = (float*)d_out;
    (void)in_sizes; (void)n_in; (void)out_size;

    cudaFuncSetAttribute(k_gemmM, cudaFuncAttributeMaxDynamicSharedMemorySize,
                         GM_SMEM);

    k_zero<<<(NN + 255) / 256, 256>>>(ei, bt);
    k_wprep<<<(6 * DD * DD + 255) / 256, 256>>>(W1, W2);
    k_count<<<(NE + 255) / 256, 256>>>(ei);
    k_scanA<<<SCAN_NB, 256>>>();
    k_scanB<<<1, 128>>>();
    k_scanC<<<SCAN_NB, 256>>>();
    k_fill<<<(NE + 255) / 256, 256>>>(ei);

    for (int l = 0; l < 3; l++) {
        int sPrev = 2 * l - 1;                    // BN2 of previous layer
        const float* gmP = (l == 0) ? g1 : (g2 + (l - 1) * DD);
        const float* btP = (l == 0) ? b1 : (b2 + (l - 1) * DD);
        k_agg<<<(NN * 32 + 255) / 256, 256>>>(x, l == 0 ? 1 : 0,
                                              l == 0 ? -1 : sPrev, gmP, btP,
                                              eps, l);
        k_gemmM<<<GM_GRID, 256, GM_SMEM>>>(0, 0, g1, b1, -1, 2 * l, 2 * l);
        k_gemmM<<<GM_GRID, 256, GM_SMEM>>>(1, 1, g1 + l * DD, b1 + l * DD,
                                           2 * l, 2 * l + 1, 2 * l + 1);
    }

    k_nodeemb<<<(NN * 32 + 255) / 256, 256>>>(out, g2 + 2 * DD, b2 + 2 * DD);
    k_counts<<<(NN + 255) / 256, 256>>>(bt);
    k_gsum<<<(NN + 255) / 256, 128>>>(out, bt);
    k_gemb<<<NG, DD>>>(out);
}

// round 10
// speedup vs baseline: 1.6396x; 1.0076x over previous
#include <cuda_runtime.h>
#include <cuda_bf16.h>
#include <cuda_fp16.h>
#include <cstdint>

// GINNet on GB300. R9: gather operand compressed to fp16 (halves k_agg L2
// traffic; fp16 copy produced by GEMM2 epilogue / x-convert pass). R8 mma.sync
// bf16-split GEMM + fused BN prologues otherwise intact.

#define NN 100000
#define NE 1600000
#define DD 128
#define NG 64

#define SCAN_CHUNK 1024
#define SCAN_NB ((NN + SCAN_CHUNK - 1) / SCAN_CHUNK)   // 98

#define GM_GRID ((NN + 127) / 128)                      // 782
#define GM_SMEM 131072

// ---------------- device scratch (allocation-free contract) ----------------
__device__ __align__(128) float g_z[NN * DD];   // aggregated features
__device__ __align__(128) float g_y[NN * DD];   // GEMM1 output (pre-BN1)
__device__ __align__(128) float g_h[NN * DD];   // GEMM2 output (pre-BN2)
__device__ __align__(128) __half g_hh[NN * DD]; // fp16 gather operand
__device__ __align__(128) unsigned char g_wblk[6][65536]; // W^T bf16 hi|lo, swizzled
__device__ int   g_cnt[NN];
__device__ int   g_ptr[NN + 1];
__device__ int   g_cur[NN];
__device__ int   g_srcs[NE];
__device__ int   g_bsum[SCAN_NB];
__device__ int   g_boff[SCAN_NB];
__device__ float g_ssum[6][DD];
__device__ float g_ssq[6][DD];
__device__ float g_gsum[NG * DD];
__device__ int   g_gcnt[NG];
__device__ int   g_flags[2];                    // [0]=edge idx is64, [1]=batch is64

// ---------------- PTX helpers ----------------
__device__ __forceinline__ uint32_t smem_u32(const void* p) {
    uint32_t a;
    asm("{ .reg .u64 t; cvta.to.shared.u64 t, %1; cvt.u32.u64 %0, t; }"
        : "=r"(a) : "l"(p));
    return a;
}
__device__ __forceinline__ void ldsm4(uint32_t* r, uint32_t addr) {
    asm volatile("ldmatrix.sync.aligned.m8n8.x4.shared.b16 {%0,%1,%2,%3}, [%4];"
                 : "=r"(r[0]), "=r"(r[1]), "=r"(r[2]), "=r"(r[3]) : "r"(addr));
}
__device__ __forceinline__ void mma16816(float* d, const uint32_t* a,
                                         const uint32_t* b) {
    asm volatile(
        "mma.sync.aligned.m16n8k16.row.col.f32.bf16.bf16.f32 "
        "{%0,%1,%2,%3}, {%4,%5,%6,%7}, {%8,%9}, {%0,%1,%2,%3};"
        : "+f"(d[0]), "+f"(d[1]), "+f"(d[2]), "+f"(d[3])
        : "r"(a[0]), "r"(a[1]), "r"(a[2]), "r"(a[3]), "r"(b[0]), "r"(b[1]));
}
__device__ __forceinline__ uint32_t pack_bf16x2(float lo, float hi) {
    __nv_bfloat16 l = __float2bfloat16(lo), h = __float2bfloat16(hi);
    return (uint32_t)__bfloat16_as_ushort(l) |
           ((uint32_t)__bfloat16_as_ushort(h) << 16);
}
__device__ __forceinline__ float4 h4_to_f4(uint2 r) {
    float2 a = __half22float2(*(const __half2*)&r.x);
    float2 b = __half22float2(*(const __half2*)&r.y);
    return make_float4(a.x, a.y, b.x, b.y);
}

// ---------------- misc helpers ----------------
__device__ __forceinline__ int get_idx(const void* p, long long i, int is64) {
    if (is64) return (int)((const long long*)p)[i];
    return ((const int*)p)[i];
}

__device__ __forceinline__ void bn_affine_block(int slot, const float* gm,
                                                const float* bt, float* sA,
                                                float* sC, int tid) {
    if (slot >= 0 && tid < DD) {
        float mean = g_ssum[slot][tid] * (1.f / NN);
        float var = g_ssq[slot][tid] * (1.f / NN) - mean * mean;
        float a = gm[tid] * rsqrtf(var + 1e-5f);
        sA[tid] = a;
        sC[tid] = bt[tid] - mean * a;
    }
}

// ---------------- setup kernels ----------------
__global__ void k_zero(const void* ei, const void* bt) {
    int i = blockIdx.x * blockDim.x + threadIdx.x;
    if (i < NN) g_cnt[i] = 0;
    if (i < 6 * DD) { ((float*)g_ssum)[i] = 0.f; ((float*)g_ssq)[i] = 0.f; }
    if (i < NG * DD) g_gsum[i] = 0.f;
    if (i < NG) g_gcnt[i] = 0;
    if (blockIdx.x == 0) {
        __shared__ int bad[2];
        if (threadIdx.x < 2) bad[threadIdx.x] = 0;
        __syncthreads();
        const long long* pe = (const long long*)ei;
        const long long* pb = (const long long*)bt;
        for (int j = threadIdx.x; j < 4096; j += blockDim.x) {
            long long v = pe[(long long)j * 390];
            if (v < 0 || v >= NN) atomicOr(&bad[0], 1);
            long long w = pb[(long long)j * 12];
            if (w < 0 || w >= NG) atomicOr(&bad[1], 1);
        }
        __syncthreads();
        if (threadIdx.x == 0) {
            g_flags[0] = bad[0] ? 0 : 1;
            g_flags[1] = bad[1] ? 0 : 1;
        }
    }
}

// x -> fp16 gather operand (layer 0)
__global__ void k_x2h(const float* __restrict__ x) {
    int i = blockIdx.x * blockDim.x + threadIdx.x;   // float4 index
    if (i >= NN * 32) return;
    float4 v = ((const float4*)x)[i];
    uint2 r;
    *(__half2*)&r.x = __floats2half2_rn(v.x, v.y);
    *(__half2*)&r.y = __floats2half2_rn(v.z, v.w);
    ((uint2*)g_hh)[i] = r;
}

// W^T split to bf16 hi/lo, [n][k] rows (256B) with xor-(n&7)<<4 swizzle.
__global__ void k_wprep(const float* __restrict__ W1, const float* __restrict__ W2) {
    int idx = blockIdx.x * blockDim.x + threadIdx.x;
    if (idx >= 6 * DD * DD) return;
    int m = idx >> 14;
    int r = idx & 16383;
    int n = r >> 7, k = r & 127;
    int l = m >> 1;
    const float* W = (m & 1) ? (W2 + l * DD * DD) : (W1 + l * DD * DD);
    float v = W[k * DD + n];
    __nv_bfloat16 h = __float2bfloat16(v);
    __nv_bfloat16 lo = __float2bfloat16(v - __bfloat162float(h));
    int off = n * 256 + k * 2;
    int sw = off ^ ((n & 7) << 4);
    *(__nv_bfloat16*)(g_wblk[m] + sw) = h;
    *(__nv_bfloat16*)(g_wblk[m] + 32768 + sw) = lo;
}

__global__ void k_count(const void* ei) {
    int e = blockIdx.x * blockDim.x + threadIdx.x;
    if (e >= NE) return;
    int t = get_idx(ei, (long long)NE + e, g_flags[0]);
    atomicAdd(&g_cnt[t], 1);
}

__global__ void k_scanA() {
    __shared__ int wsum[8];
    int b = blockIdx.x, tid = threadIdx.x;
    int base = b * SCAN_CHUNK + tid * 4;
    int s = 0;
#pragma unroll
    for (int j = 0; j < 4; j++) { int i = base + j; if (i < NN) s += g_cnt[i]; }
#pragma unroll
    for (int o = 16; o > 0; o >>= 1) s += __shfl_xor_sync(0xffffffffu, s, o);
    if ((tid & 31) == 0) wsum[tid >> 5] = s;
    __syncthreads();
    if (tid == 0) {
        int t = 0;
#pragma unroll
        for (int w = 0; w < 8; w++) t += wsum[w];
        g_bsum[b] = t;
    }
}

__global__ void k_scanB() {
    __shared__ int sh[128];
    int t = threadIdx.x;
    sh[t] = (t < SCAN_NB) ? g_bsum[t] : 0;
    __syncthreads();
#pragma unroll
    for (int off = 1; off < 128; off <<= 1) {
        int v = (t >= off) ? sh[t - off] : 0;
        __syncthreads();
        sh[t] += v;
        __syncthreads();
    }
    if (t < SCAN_NB) g_boff[t] = (t == 0) ? 0 : sh[t - 1];
}

__global__ void k_scanC() {
    __shared__ int wexc[8];
    int b = blockIdx.x, tid = threadIdx.x;
    int lane = tid & 31, wid = tid >> 5;
    int base = b * SCAN_CHUNK + tid * 4;
    int c[4];
    int tsum = 0;
#pragma unroll
    for (int j = 0; j < 4; j++) {
        int i = base + j;
        c[j] = (i < NN) ? g_cnt[i] : 0;
        tsum += c[j];
    }
    int incl = tsum;
#pragma unroll
    for (int o = 1; o < 32; o <<= 1) {
        int v = __shfl_up_sync(0xffffffffu, incl, o);
        if (lane >= o) incl += v;
    }
    if (lane == 31) wexc[wid] = incl;
    __syncthreads();
    if (tid == 0) {
        int run = 0;
#pragma unroll
        for (int w = 0; w < 8; w++) { int v = wexc[w]; wexc[w] = run; run += v; }
    }
    __syncthreads();
    int p = g_boff[b] + wexc[wid] + (incl - tsum);
#pragma unroll
    for (int j = 0; j < 4; j++) {
        int i = base + j;
        if (i < NN) {
            g_ptr[i] = p; g_cur[i] = p; p += c[j];
            if (i == NN - 1) g_ptr[NN] = p;
        }
    }
}

__global__ void k_fill(const void* ei) {
    int e = blockIdx.x * blockDim.x + threadIdx.x;
    if (e >= NE) return;
    int is64 = g_flags[0];
    int s = get_idx(ei, e, is64);
    int t = get_idx(ei, (long long)NE + e, is64);
    int pos = atomicAdd(&g_cur[t], 1);
    g_srcs[pos] = s;
}

// ---------------- aggregation: warp per node, fp16 gather operand ----------
__global__ void k_agg(int slot, const float* __restrict__ gm,
                      const float* __restrict__ bt,
                      const float* __restrict__ epsArr, int layer) {
    __shared__ __align__(16) float sAf[DD], sCf[DD];
    int tid = threadIdx.x;
    bn_affine_block(slot, gm, bt, sAf, sCf, tid);
    __syncthreads();

    int gt = blockIdx.x * blockDim.x + tid;
    int node = gt >> 5;
    int lane = gt & 31;
    if (node >= NN) return;
    const uint2* hin = (const uint2*)g_hh;
    float4 ca, cc;
    if (slot >= 0) {
        ca = ((const float4*)sAf)[lane];
        cc = ((const float4*)sCf)[lane];
    }
    float epsl = 1.f + epsArr[layer];
    int beg = g_ptr[node], end = g_ptr[node + 1];
    float4 v = h4_to_f4(hin[node * 32 + lane]);
    if (slot >= 0) {
        v.x = fmaxf(fmaf(v.x, ca.x, cc.x), 0.f);
        v.y = fmaxf(fmaf(v.y, ca.y, cc.y), 0.f);
        v.z = fmaxf(fmaf(v.z, ca.z, cc.z), 0.f);
        v.w = fmaxf(fmaf(v.w, ca.w, cc.w), 0.f);
    }
    float4 acc = make_float4(v.x * epsl, v.y * epsl, v.z * epsl, v.w * epsl);
    for (int e = beg; e < end; e++) {
        int s = __ldg(&g_srcs[e]);
        float4 u = h4_to_f4(hin[s * 32 + lane]);
        if (slot >= 0) {
            u.x = fmaxf(fmaf(u.x, ca.x, cc.x), 0.f);
            u.y = fmaxf(fmaf(u.y, ca.y, cc.y), 0.f);
            u.z = fmaxf(fmaf(u.z, ca.z, cc.z), 0.f);
            u.w = fmaxf(fmaf(u.w, ca.w, cc.w), 0.f);
        }
        acc.x += u.x; acc.y += u.y; acc.z += u.z; acc.w += u.w;
    }
    ((float4*)g_z)[node * 32 + lane] = acc;
}

// ---------------- mma.sync GEMM: Y[128x128 tile] = act(A) @ W ---------------
__global__ __launch_bounds__(256, 1)
void k_gemmM(int srcSel, int dstSel, const float* __restrict__ gm,
             const float* __restrict__ bt, int actSlot, int statSlot, int wsel,
             int dumpH) {
    extern __shared__ unsigned char dyn[];
    __shared__ float cs[DD], cq[DD];
    __shared__ __align__(16) float sAf[DD], sCf[DD];
    unsigned char* Ahi = dyn;
    unsigned char* Alo = dyn + 32768;
    unsigned char* Bhi = dyn + 65536;

    int tid = threadIdx.x;
    int wid = tid >> 5, lane = tid & 31;
    int mBase = blockIdx.x * 128;
    const float* A = srcSel ? g_y : g_z;
    float* Y = dstSel ? g_h : g_y;

    if (tid < DD) { cs[tid] = 0.f; cq[tid] = 0.f; }
    bn_affine_block(actSlot, gm, bt, sAf, sCf, tid);

    // stage B: 64KB coalesced copy (hi|lo pre-swizzled, contiguous)
    {
        const float4* src = (const float4*)g_wblk[wsel];
        float4* dst = (float4*)Bhi;
#pragma unroll
        for (int i = 0; i < 16; i++) dst[tid + i * 256] = src[tid + i * 256];
    }
    __syncthreads();

    // stage A: 2 threads per row, 64 cols each; act + split + swizzled store
    {
        int r = tid >> 1, ch = tid & 1;
        int grow = mBase + r;
        bool valid = grow < NN;
        const float4* A4 = (const float4*)A;
#pragma unroll
        for (int c = 0; c < 8; c++) {
            int f4i = ch * 16 + c * 2;
            float4 v0 = make_float4(0.f, 0.f, 0.f, 0.f);
            float4 v1 = v0;
            if (valid) {
                v0 = A4[grow * 32 + f4i];
                v1 = A4[grow * 32 + f4i + 1];
            }
            if (actSlot >= 0 && valid) {
                float4 a0 = ((const float4*)sAf)[f4i];
                float4 c0 = ((const float4*)sCf)[f4i];
                float4 a1 = ((const float4*)sAf)[f4i + 1];
                float4 c1 = ((const float4*)sCf)[f4i + 1];
                v0.x = fmaxf(fmaf(v0.x, a0.x, c0.x), 0.f);
                v0.y = fmaxf(fmaf(v0.y, a0.y, c0.y), 0.f);
                v0.z = fmaxf(fmaf(v0.z, a0.z, c0.z), 0.f);
                v0.w = fmaxf(fmaf(v0.w, a0.w, c0.w), 0.f);
                v1.x = fmaxf(fmaf(v1.x, a1.x, c1.x), 0.f);
                v1.y = fmaxf(fmaf(v1.y, a1.y, c1.y), 0.f);
                v1.z = fmaxf(fmaf(v1.z, a1.z, c1.z), 0.f);
                v1.w = fmaxf(fmaf(v1.w, a1.w, c1.w), 0.f);
            }
            float f[8] = {v0.x, v0.y, v0.z, v0.w, v1.x, v1.y, v1.z, v1.w};
            uint4 hi, lo;
            uint32_t* hp = (uint32_t*)&hi;
            uint32_t* lp = (uint32_t*)&lo;
#pragma unroll
            for (int j = 0; j < 4; j++) {
                float x0 = f[j * 2], x1 = f[j * 2 + 1];
                __nv_bfloat16 h0 = __float2bfloat16(x0);
                __nv_bfloat16 h1 = __float2bfloat16(x1);
                hp[j] = (uint32_t)__bfloat16_as_ushort(h0) |
                        ((uint32_t)__bfloat16_as_ushort(h1) << 16);
                lp[j] = pack_bf16x2(x0 - __bfloat162float(h0),
                                    x1 - __bfloat162float(h1));
            }
            int off = r * 256 + (ch * 8 + c) * 16;
            int sw = off ^ ((r & 7) << 4);
            *(uint4*)(Ahi + sw) = hi;
            *(uint4*)(Alo + sw) = lo;
        }
    }
    __syncthreads();

    // ---- mma mainloop ----
    float acc[16][4];
#pragma unroll
    for (int n = 0; n < 16; n++)
#pragma unroll
        for (int j = 0; j < 4; j++) acc[n][j] = 0.f;

    int wrow = wid * 16;
    uint32_t aU = smem_u32(Ahi), bU = smem_u32(Bhi);
    int arow = wrow + (lane & 15);
    int akh = (lane >> 4) & 1;
    int aswb = ((arow & 7) << 4);
    int ntp = (lane >> 4) & 1;
    int bkh = (lane >> 3) & 1;
    int brow = lane & 7;
    int bswb = (brow << 4);

#pragma unroll
    for (int k = 0; k < 8; k++) {
        uint32_t afH[4], afL[4];
        {
            int aoff = arow * 256 + k * 32 + akh * 16;
            ldsm4(afH, aU + (uint32_t)(aoff ^ aswb));
            ldsm4(afL, aU + 32768u + (uint32_t)(aoff ^ aswb));
        }
        uint32_t bf[32];
#pragma unroll
        for (int p = 0; p < 8; p++) {
            int boff = ((2 * p + ntp) * 8 + brow) * 256 + k * 32 + bkh * 16;
            ldsm4(&bf[p * 4], bU + (uint32_t)(boff ^ bswb));
        }
#pragma unroll
        for (int p = 0; p < 8; p++) {           // hi * hi
            mma16816(acc[2 * p], afH, &bf[4 * p]);
            mma16816(acc[2 * p + 1], afH, &bf[4 * p + 2]);
        }
#pragma unroll
        for (int p = 0; p < 8; p++) {           // lo * hi
            mma16816(acc[2 * p], afL, &bf[4 * p]);
            mma16816(acc[2 * p + 1], afL, &bf[4 * p + 2]);
        }
#pragma unroll
        for (int p = 0; p < 8; p++) {
            int boff = ((2 * p + ntp) * 8 + brow) * 256 + k * 32 + bkh * 16;
            ldsm4(&bf[p * 4], bU + 32768u + (uint32_t)(boff ^ bswb));
        }
#pragma unroll
        for (int p = 0; p < 8; p++) {           // hi * lo
            mma16816(acc[2 * p], afH, &bf[4 * p]);
            mma16816(acc[2 * p + 1], afH, &bf[4 * p + 2]);
        }
    }

    // ---- epilogue: store Y (+ optional fp16 dump) + BN column stats ----
    int r0 = mBase + wrow + (lane >> 2);
    int r1 = r0 + 8;
#pragma unroll
    for (int n = 0; n < 16; n++) {
        int col = n * 8 + 2 * (lane & 3);
        if (r0 < NN) {
            *(float2*)&Y[r0 * DD + col] = make_float2(acc[n][0], acc[n][1]);
            if (dumpH)
                *(__half2*)&g_hh[r0 * DD + col] =
                    __floats2half2_rn(acc[n][0], acc[n][1]);
        }
        if (r1 < NN) {
            *(float2*)&Y[r1 * DD + col] = make_float2(acc[n][2], acc[n][3]);
            if (dumpH)
                *(__half2*)&g_hh[r1 * DD + col] =
                    __floats2half2_rn(acc[n][2], acc[n][3]);
        }
        float s0 = acc[n][0] + acc[n][2];
        float s1 = acc[n][1] + acc[n][3];
        float q0 = acc[n][0] * acc[n][0] + acc[n][2] * acc[n][2];
        float q1 = acc[n][1] * acc[n][1] + acc[n][3] * acc[n][3];
#pragma unroll
        for (int o = 4; o <= 16; o <<= 1) {
            s0 += __shfl_xor_sync(0xffffffffu, s0, o);
            s1 += __shfl_xor_sync(0xffffffffu, s1, o);
            q0 += __shfl_xor_sync(0xffffffffu, q0, o);
            q1 += __shfl_xor_sync(0xffffffffu, q1, o);
        }
        if (lane < 4) {
            int c2 = n * 8 + 2 * lane;
            atomicAdd(&cs[c2], s0);
            atomicAdd(&cs[c2 + 1], s1);
            atomicAdd(&cq[c2], q0);
            atomicAdd(&cq[c2 + 1], q1);
        }
    }
    __syncthreads();
    if (tid < DD) {
        atomicAdd(&g_ssum[statSlot][tid], cs[tid]);
        atomicAdd(&g_ssq[statSlot][tid], cq[tid]);
    }
}

// ---------------- readout ----------------
__global__ void k_nodeemb(float* __restrict__ out, const float* __restrict__ gm,
                          const float* __restrict__ bt) {
    __shared__ __align__(16) float sAf[DD], sCf[DD];
    int tid = threadIdx.x;
    bn_affine_block(5, gm, bt, sAf, sCf, tid);
    __syncthreads();
    int i = blockIdx.x * blockDim.x + tid;
    if (i >= NN * 32) return;
    int c4 = i & 31;
    float4 v = ((const float4*)g_h)[i];
    float4 a = ((const float4*)sAf)[c4];
    float4 c = ((const float4*)sCf)[c4];
    v.x = fmaxf(fmaf(v.x, a.x, c.x), 0.f);
    v.y = fmaxf(fmaf(v.y, a.y, c.y), 0.f);
    v.z = fmaxf(fmaf(v.z, a.z, c.z), 0.f);
    v.w = fmaxf(fmaf(v.w, a.w, c.w), 0.f);
    ((float4*)out)[i] = v;
}

__global__ void k_counts(const void* bt) {
    __shared__ int hist[NG];
    int tid = threadIdx.x;
    if (tid < NG) hist[tid] = 0;
    __syncthreads();
    int i = blockIdx.x * blockDim.x + tid;
    if (i < NN) {
        int b = get_idx(bt, i, g_flags[1]);
        atomicAdd(&hist[b], 1);
    }
    __syncthreads();
    if (tid < NG && hist[tid]) atomicAdd(&g_gcnt[tid], hist[tid]);
}

__global__ void k_gsum(const float* __restrict__ emb, const void* bt) {
    int d = threadIdx.x;
    int beg = blockIdx.x * 256;
    int end = min(beg + 256, NN);
    if (beg >= NN) return;
    int is64 = g_flags[1];
    int cur = get_idx(bt, beg, is64);
    float acc = 0.f;
    for (int i = beg; i < end; i++) {
        int b = get_idx(bt, i, is64);
        if (b != cur) { atomicAdd(&g_gsum[cur * DD + d], acc); acc = 0.f; cur = b; }
        acc += emb[i * DD + d];
    }
    atomicAdd(&g_gsum[cur * DD + d], acc);
}

__global__ void k_gemb(float* __restrict__ out) {
    int g = blockIdx.x, d = threadIdx.x;
    float cnt = (float)g_gcnt[g];
    float v = g_gsum[g * DD + d] / fmaxf(cnt, 1.f);
    float s = v * v;
#pragma unroll
    for (int o = 16; o > 0; o >>= 1) s += __shfl_xor_sync(0xffffffffu, s, o);
    __shared__ float red[4];
    if ((d & 31) == 0) red[d >> 5] = s;
    __syncthreads();
    float tot = red[0] + red[1] + red[2] + red[3];
    float nrm = fmaxf(sqrtf(tot), 1e-12f);
    out[NN * DD + g * DD + d] = v / nrm;
}

// ---------------- launch ----------------
extern "C" void kernel_launch(void* const* d_in, const int* in_sizes, int n_in,
                              void* d_out, int out_size) {
    const float* x  = (const float*)d_in[0];
    const void*  ei = d_in[1];
    const void*  bt = d_in[2];
    const float* W1 = (const float*)d_in[3];
    const float* g1 = (const float*)d_in[4];
    const float* b1 = (const float*)d_in[5];
    const float* W2 = (const float*)d_in[6];
    const float* g2 = (const float*)d_in[7];
    const float* b2 = (const float*)d_in[8];
    const float* eps = (const float*)d_in[9];
    float* out = (float*)d_out;
    (void)in_sizes; (void)n_in; (void)out_size;

    cudaFuncSetAttribute(k_gemmM, cudaFuncAttributeMaxDynamicSharedMemorySize,
                         GM_SMEM);

    k_zero<<<(NN + 255) / 256, 256>>>(ei, bt);
    k_x2h<<<(NN * 32 + 255) / 256, 256>>>(x);
    k_wprep<<<(6 * DD * DD + 255) / 256, 256>>>(W1, W2);
    k_count<<<(NE + 255) / 256, 256>>>(ei);
    k_scanA<<<SCAN_NB, 256>>>();
    k_scanB<<<1, 128>>>();
    k_scanC<<<SCAN_NB, 256>>>();
    k_fill<<<(NE + 255) / 256, 256>>>(ei);

    for (int l = 0; l < 3; l++) {
        int sPrev = 2 * l - 1;                    // BN2 of previous layer
        const float* gmP = (l == 0) ? g1 : (g2 + (l - 1) * DD);
        const float* btP = (l == 0) ? b1 : (b2 + (l - 1) * DD);
        k_agg<<<(NN * 32 + 255) / 256, 256>>>(l == 0 ? -1 : sPrev, gmP, btP,
                                              eps, l);
        k_gemmM<<<GM_GRID, 256, GM_SMEM>>>(0, 0, g1, b1, -1, 2 * l, 2 * l, 0);
        k_gemmM<<<GM_GRID, 256, GM_SMEM>>>(1, 1, g1 + l * DD, b1 + l * DD,
                                           2 * l, 2 * l + 1, 2 * l + 1,
                                           l < 2 ? 1 : 0);
    }

    k_nodeemb<<<(NN * 32 + 255) / 256, 256>>>(out, g2 + 2 * DD, b2 + 2 * DD);
    k_counts<<<(NN + 255) / 256, 256>>>(bt);
    k_gsum<<<(NN + 255) / 256, 128>>>(out, bt);
    k_gemb<<<NG, DD>>>(out);
}